// round 1
// baseline (speedup 1.0000x reference)
#include <cuda_runtime.h>
#include <math.h>
#include <stdint.h>

#define NROWS 32768
#define DDIM  256
#define KCB   1024
#define MT    64
#define KT    128
#define DC    16

// 134 MB distance scratch + small accumulators (static device arrays: allowed)
__device__ float  g_dist[(size_t)NROWS * KCB];
__device__ float  g_b2[KCB];
__device__ float  g_avgp[KCB];
__device__ double g_sample;
__device__ double g_msum;

// ---------------------------------------------------------------- K0: init
__global__ void k0_init(const float* __restrict__ cb) {
    int t = blockIdx.x * blockDim.x + threadIdx.x;
    if (t < KCB) {
        const float4* r = (const float4*)(cb + (size_t)t * DDIM);
        double acc = 0.0;
        for (int i = 0; i < DDIM / 4; i++) {
            float4 v = r[i];
            acc += (double)v.x * v.x + (double)v.y * v.y
                 + (double)v.z * v.z + (double)v.w * v.w;
        }
        g_b2[t]   = (float)acc;
        g_avgp[t] = 0.0f;
    }
    if (t == 0) { g_sample = 0.0; g_msum = 0.0; }
}

// ------------------------------------------- K1: fused fp32 GEMM + argmin + gather
__global__ __launch_bounds__(256)
void k1_main(const float* __restrict__ x, const float* __restrict__ cb,
             float* __restrict__ out, int write_aux) {
    __shared__ float  As[DC][68];     // A chunk, d-major (padded)
    __shared__ float  Bs[DC][132];    // B chunk, d-major (padded)
    __shared__ float  a2s[MT];
    __shared__ float  b2s[KT];
    __shared__ float  rmind[MT];
    __shared__ int    rmini[MT];
    __shared__ double sred[8];

    const int tid  = threadIdx.x;
    const int tx   = tid & 15;        // 16 col-groups of 8
    const int ty   = tid >> 4;        // 16 row-groups of 4
    const int row0 = blockIdx.x * MT;

    // per-row |x|^2 (double-accumulated -> fp32; constant-per-row error cancels in argmin)
    if (tid < MT) {
        const float4* r = (const float4*)(x + (size_t)(row0 + tid) * DDIM);
        double acc = 0.0;
        for (int i = 0; i < DDIM / 4; i++) {
            float4 v = r[i];
            acc += (double)v.x * v.x + (double)v.y * v.y
                 + (double)v.z * v.z + (double)v.w * v.w;
        }
        a2s[tid]   = (float)acc;
        rmind[tid] = 3.402823466e38f;
        rmini[tid] = 0;
    }
    __syncthreads();

    for (int kc = 0; kc < KCB / KT; kc++) {
        __syncthreads();                       // prior epilogue done with b2s
        if (tid < KT) b2s[tid] = g_b2[kc * KT + tid];

        float acc[4][8];
        #pragma unroll
        for (int i = 0; i < 4; i++)
            #pragma unroll
            for (int j = 0; j < 8; j++) acc[i][j] = 0.0f;

        for (int d0 = 0; d0 < DDIM; d0 += DC) {
            __syncthreads();
            {   // load A chunk: 64 rows x 16 d
                int arow = tid >> 2, dg = (tid & 3) << 2;
                float4 v = *(const float4*)(x + (size_t)(row0 + arow) * DDIM + d0 + dg);
                As[dg + 0][arow] = v.x; As[dg + 1][arow] = v.y;
                As[dg + 2][arow] = v.z; As[dg + 3][arow] = v.w;
            }
            {   // load B chunk: 128 cols x 16 d
                int bcol = tid >> 1, dg = (tid & 1) << 3;
                const float* src = cb + (size_t)(kc * KT + bcol) * DDIM + d0 + dg;
                float4 v0 = *(const float4*)src;
                float4 v1 = *(const float4*)(src + 4);
                Bs[dg + 0][bcol] = v0.x; Bs[dg + 1][bcol] = v0.y;
                Bs[dg + 2][bcol] = v0.z; Bs[dg + 3][bcol] = v0.w;
                Bs[dg + 4][bcol] = v1.x; Bs[dg + 5][bcol] = v1.y;
                Bs[dg + 6][bcol] = v1.z; Bs[dg + 7][bcol] = v1.w;
            }
            __syncthreads();
            #pragma unroll
            for (int dd = 0; dd < DC; dd++) {
                float4 av  = *(const float4*)&As[dd][ty << 2];
                float4 bv0 = *(const float4*)&Bs[dd][tx << 3];
                float4 bv1 = *(const float4*)&Bs[dd][(tx << 3) + 4];
                float a[4] = {av.x, av.y, av.z, av.w};
                float b[8] = {bv0.x, bv0.y, bv0.z, bv0.w, bv1.x, bv1.y, bv1.z, bv1.w};
                #pragma unroll
                for (int i = 0; i < 4; i++)
                    #pragma unroll
                    for (int j = 0; j < 8; j++)
                        acc[i][j] = fmaf(a[i], b[j], acc[i][j]);
            }
        }

        // epilogue for this k-chunk: dist (reference rounding order), store, running argmin
        #pragma unroll
        for (int i = 0; i < 4; i++) {
            int rr   = (ty << 2) + i;
            int grow = row0 + rr;
            float a2 = a2s[rr];
            float best = 3.402823466e38f;
            int bcol = 0;
            float dv[8];
            #pragma unroll
            for (int j = 0; j < 8; j++) {
                int col = (tx << 3) + j;
                float t = a2 + b2s[col];          // fl(a2 + b2)
                float d = t - 2.0f * acc[i][j];   // fl(t - 2ab)
                dv[j] = d;
                if (d < best) { best = d; bcol = kc * KT + col; }  // first-index ties
            }
            float4* dst = (float4*)(g_dist + (size_t)grow * KCB + kc * KT + (tx << 3));
            dst[0] = make_float4(dv[0], dv[1], dv[2], dv[3]);
            dst[1] = make_float4(dv[4], dv[5], dv[6], dv[7]);
            #pragma unroll
            for (int off = 8; off >= 1; off >>= 1) {   // lexicographic (d, idx) min over 16 lanes
                float od = __shfl_xor_sync(0xffffffffu, best, off);
                int   oc = __shfl_xor_sync(0xffffffffu, bcol, off);
                if (od < best || (od == best && oc < bcol)) { best = od; bcol = oc; }
            }
            if (tx == 0) {
                if (best < rmind[rr] || (best == rmind[rr] && bcol < rmini[rr])) {
                    rmind[rr] = best; rmini[rr] = bcol;
                }
            }
        }
    }
    __syncthreads();

    // gather codebook[argmin], write quantized_st = fl(x + fl(q-x)), accumulate sq
    double lsq = 0.0;
    for (int it = 0; it < MT; it++) {
        int grow = row0 + it;
        int idx  = rmini[it];
        float xv   = x[(size_t)grow * DDIM + tid];
        float q    = cb[(size_t)idx * DDIM + tid];
        float diff = q - xv;
        out[(size_t)grow * DDIM + tid] = xv + diff;
        lsq += (double)diff * (double)diff;
    }
    if (write_aux && tid < MT)
        out[(size_t)NROWS * DDIM + 1 + row0 + tid] = (float)rmini[tid];

    #pragma unroll
    for (int off = 16; off >= 1; off >>= 1)
        lsq += __shfl_xor_sync(0xffffffffu, lsq, off);
    if ((tid & 31) == 0) sred[tid >> 5] = lsq;
    __syncthreads();
    if (tid == 0) {
        double s = 0.0;
        for (int i = 0; i < 8; i++) s += sred[i];
        atomicAdd(&g_msum, s);
    }
}

// ---------------------------------------------- K2: softmax entropy pass (warp/row)
__global__ __launch_bounds__(256)
void k2_soft() {
    int warp = (blockIdx.x * 256 + threadIdx.x) >> 5;
    int lane = threadIdx.x & 31;
    const float* dr = g_dist + (size_t)warp * KCB;

    float l[32];
    float M = -3.402823466e38f;
    #pragma unroll
    for (int i = 0; i < 32; i++) {
        float d = dr[lane + (i << 5)];
        float v = (-d) / 0.01f;            // IEEE division, matches flat/temperature
        l[i] = v;
        M = fmaxf(M, v);
    }
    #pragma unroll
    for (int off = 16; off >= 1; off >>= 1)
        M = fmaxf(M, __shfl_xor_sync(0xffffffffu, M, off));

    float S = 0.0f;
    #pragma unroll
    for (int i = 0; i < 32; i++) S += expf(l[i] - M);
    #pragma unroll
    for (int off = 16; off >= 1; off >>= 1)
        S += __shfl_xor_sync(0xffffffffu, S, off);

    float logS = logf(S);
    float accent = 0.0f;
    #pragma unroll
    for (int i = 0; i < 32; i++) {
        float sh = l[i] - M;
        float p  = expf(sh) / S;
        accent += p * (sh - logS);          // p * log_softmax (the +1e-5 is an fp32 no-op here)
        if (p > 0.0f) atomicAdd(&g_avgp[lane + (i << 5)], p);  // zeros are no-ops: skip
    }
    #pragma unroll
    for (int off = 16; off >= 1; off >>= 1)
        accent += __shfl_xor_sync(0xffffffffu, accent, off);
    if (lane == 0) atomicAdd(&g_sample, (double)accent);
}

// ---------------------------------------------------------------- K3: final loss
__global__ void k3_final(float* out, int write_loss) {
    __shared__ float w[32];
    int t = threadIdx.x;   // 1024 threads
    float ap   = g_avgp[t] / 32768.0f;
    float term = ap * logf(ap + 1e-5f);
    #pragma unroll
    for (int off = 16; off >= 1; off >>= 1)
        term += __shfl_xor_sync(0xffffffffu, term, off);
    if ((t & 31) == 0) w[t >> 5] = term;
    __syncthreads();
    if (t == 0) {
        float tot = 0.0f;
        for (int i = 0; i < 32; i++) tot += w[i];
        float avg_ent = -tot;
        float samp    = -(float)(g_sample / 32768.0);
        float entropy = samp - avg_ent;
        float m       = (float)(g_msum / 8388608.0);
        float loss    = (m * 0.25f + m) + entropy * 0.1f;
        if (write_loss) out[(size_t)NROWS * DDIM] = loss;
    }
}

// ---------------------------------------------------------------- launch
extern "C" void kernel_launch(void* const* d_in, const int* in_sizes, int n_in,
                              void* d_out, int out_size) {
    const float* x  = (const float*)d_in[0];
    const float* cb = (const float*)d_in[1];
    if (n_in >= 2 && in_sizes[0] == KCB * DDIM && in_sizes[1] == NROWS * DDIM) {
        // defensive: inputs arrived (codebook, x)
        const float* tmp = x; x = cb; cb = tmp;
    }
    float* out = (float*)d_out;
    int aux = (out_size >= NROWS * DDIM + 1 + NROWS) ? 1 : 0;

    k0_init<<<4, 256>>>(cb);
    k1_main<<<NROWS / MT, 256>>>(x, cb, out, aux);
    k2_soft<<<NROWS / 8, 256>>>();
    k3_final<<<1, 1024>>>(out, (out_size > NROWS * DDIM) ? 1 : 0);
}

// round 2
// speedup vs baseline: 1.2323x; 1.2323x over previous
#include <cuda_runtime.h>
#include <math.h>
#include <stdint.h>

#define NROWS 32768
#define DDIM  256
#define KCB   1024
#define MT    64
#define KT    128
#define DCB   32

// 134 MB distance scratch + per-row min + small accumulators
__device__ float  g_dist[(size_t)NROWS * KCB];
__device__ float  g_rmin[NROWS];
__device__ float  g_b2[KCB];
__device__ float  g_avgp[KCB];
__device__ double g_sample;
__device__ double g_msum;

// ---------------------------------------------------------------- K0: init
__global__ void k0_init(const float* __restrict__ cb) {
    int t = blockIdx.x * blockDim.x + threadIdx.x;
    if (t < KCB) {
        const float4* r = (const float4*)(cb + (size_t)t * DDIM);
        double acc = 0.0;
        for (int i = 0; i < DDIM / 4; i++) {
            float4 v = r[i];
            acc += (double)v.x * v.x + (double)v.y * v.y
                 + (double)v.z * v.z + (double)v.w * v.w;
        }
        g_b2[t]   = (float)acc;
        g_avgp[t] = 0.0f;
    }
    if (t == 0) { g_sample = 0.0; g_msum = 0.0; }
}

// ------------------------------------------- K1: fused fp32 GEMM + argmin + gather
struct K1Smem {
    float  As[DDIM][MT + 4];       // full A tile, d-major (68 per row: float4-aligned pad)
    float  Bs[2][DCB][KT + 4];     // double-buffered B chunk, d-major (132)
    float  b2s[KCB];
    float  a2s[MT];
    float  rmind[MT];
    int    rmini[MT];
    double sred[8];
};

__global__ __launch_bounds__(256, 2)
void k1_main(const float* __restrict__ x, const float* __restrict__ cb,
             float* __restrict__ out, int write_aux) {
    extern __shared__ char smem_raw[];
    K1Smem* S = (K1Smem*)smem_raw;

    const int tid  = threadIdx.x;
    const int tx   = tid & 15;        // 16 col-groups of 8
    const int ty   = tid >> 4;        // 16 row-groups of 4
    const int row0 = blockIdx.x * MT;

    // ---- one-time staging ----
    // full b2
    #pragma unroll
    for (int i = 0; i < KCB / 256; i++) S->b2s[tid + i * 256] = g_b2[tid + i * 256];

    // full A tile: thread (row = tid>>2, chunk = tid&3) loads 64 d-values of its row
    {
        int arow  = tid >> 2;
        int dbase = (tid & 3) << 6;
        const float4* src = (const float4*)(x + (size_t)(row0 + arow) * DDIM + dbase);
        #pragma unroll
        for (int q = 0; q < 16; q++) {
            float4 v = src[q];
            int d = dbase + (q << 2);
            S->As[d + 0][arow] = v.x; S->As[d + 1][arow] = v.y;
            S->As[d + 2][arow] = v.z; S->As[d + 3][arow] = v.w;
        }
    }

    // per-row |x|^2 (double-accumulated; constant-per-row error cancels in argmin)
    if (tid < MT) {
        const float4* r = (const float4*)(x + (size_t)(row0 + tid) * DDIM);
        double acc = 0.0;
        #pragma unroll 4
        for (int i = 0; i < DDIM / 4; i++) {
            float4 v = r[i];
            acc += (double)v.x * v.x + (double)v.y * v.y
                 + (double)v.z * v.z + (double)v.w * v.w;
        }
        S->a2s[tid]   = (float)acc;
        S->rmind[tid] = 3.402823466e38f;
        S->rmini[tid] = 0;
    }

    // prefetch B phase 0 and store
    const int bcol = tid >> 1;
    const int bd0  = (tid & 1) << 4;  // 0 or 16
    float4 rB[4];
    {
        const float4* src = (const float4*)(cb + (size_t)bcol * DDIM + bd0);
        #pragma unroll
        for (int q = 0; q < 4; q++) rB[q] = src[q];
        #pragma unroll
        for (int q = 0; q < 4; q++) {
            int d = bd0 + (q << 2);
            S->Bs[0][d + 0][bcol] = rB[q].x; S->Bs[0][d + 1][bcol] = rB[q].y;
            S->Bs[0][d + 2][bcol] = rB[q].z; S->Bs[0][d + 3][bcol] = rB[q].w;
        }
    }
    __syncthreads();

    float acc[4][8];
    const int NPH = (KCB / KT) * (DDIM / DCB);   // 64 phases

    for (int p = 0; p < NPH; p++) {
        // prefetch next B chunk into registers (global -> regs, overlapped with compute)
        if (p + 1 < NPH) {
            int kc = (p + 1) >> 3, d0 = ((p + 1) & 7) << 5;
            const float4* src = (const float4*)(cb + (size_t)(kc * KT + bcol) * DDIM + d0 + bd0);
            #pragma unroll
            for (int q = 0; q < 4; q++) rB[q] = src[q];
        }

        if ((p & 7) == 0) {
            #pragma unroll
            for (int i = 0; i < 4; i++)
                #pragma unroll
                for (int j = 0; j < 8; j++) acc[i][j] = 0.0f;
        }

        const int d0  = (p & 7) << 5;
        const int buf = p & 1;
        #pragma unroll
        for (int dd = 0; dd < DCB; dd++) {
            float4 av = *(const float4*)&S->As[d0 + dd][ty << 2];
            float4 b0 = *(const float4*)&S->Bs[buf][dd][tx << 3];
            float4 b1 = *(const float4*)&S->Bs[buf][dd][(tx << 3) + 4];
            float a[4] = {av.x, av.y, av.z, av.w};
            float b[8] = {b0.x, b0.y, b0.z, b0.w, b1.x, b1.y, b1.z, b1.w};
            #pragma unroll
            for (int i = 0; i < 4; i++)
                #pragma unroll
                for (int j = 0; j < 8; j++)
                    acc[i][j] = fmaf(a[i], b[j], acc[i][j]);
        }

        if ((p & 7) == 7) {
            // epilogue for k-chunk kc: dist (reference rounding order), store, running argmin
            int kc = p >> 3;
            #pragma unroll
            for (int i = 0; i < 4; i++) {
                int rr   = (ty << 2) + i;
                int grow = row0 + rr;
                float a2 = S->a2s[rr];
                float best = 3.402823466e38f;
                int bc = 0;
                float dv[8];
                #pragma unroll
                for (int j = 0; j < 8; j++) {
                    int col = (tx << 3) + j;
                    float t = a2 + S->b2s[kc * KT + col];   // fl(a2 + b2)
                    float d = t - 2.0f * acc[i][j];         // fl(t - 2ab)
                    dv[j] = d;
                    if (d < best) { best = d; bc = kc * KT + col; }  // first-index ties
                }
                float4* dst = (float4*)(g_dist + (size_t)grow * KCB + kc * KT + (tx << 3));
                dst[0] = make_float4(dv[0], dv[1], dv[2], dv[3]);
                dst[1] = make_float4(dv[4], dv[5], dv[6], dv[7]);
                #pragma unroll
                for (int off = 8; off >= 1; off >>= 1) {   // lexicographic (d, idx) min
                    float od = __shfl_xor_sync(0xffffffffu, best, off);
                    int   oc = __shfl_xor_sync(0xffffffffu, bc, off);
                    if (od < best || (od == best && oc < bc)) { best = od; bc = oc; }
                }
                if (tx == 0) {
                    if (best < S->rmind[rr] || (best == S->rmind[rr] && bc < S->rmini[rr])) {
                        S->rmind[rr] = best; S->rmini[rr] = bc;
                    }
                }
            }
        }

        // store prefetched regs to the other buffer
        if (p + 1 < NPH) {
            int ob = (p + 1) & 1;
            #pragma unroll
            for (int q = 0; q < 4; q++) {
                int d = bd0 + (q << 2);
                S->Bs[ob][d + 0][bcol] = rB[q].x; S->Bs[ob][d + 1][bcol] = rB[q].y;
                S->Bs[ob][d + 2][bcol] = rB[q].z; S->Bs[ob][d + 3][bcol] = rB[q].w;
            }
        }
        __syncthreads();
    }

    // export per-row min for K2
    if (tid < MT) g_rmin[row0 + tid] = S->rmind[tid];

    // gather codebook[argmin], write quantized_st = fl(x + fl(q-x)), accumulate sq
    double lsq = 0.0;
    for (int it = 0; it < MT; it++) {
        int grow = row0 + it;
        int idx  = S->rmini[it];
        float xv   = x[(size_t)grow * DDIM + tid];
        float q    = cb[(size_t)idx * DDIM + tid];
        float diff = q - xv;
        out[(size_t)grow * DDIM + tid] = xv + diff;
        lsq += (double)diff * (double)diff;
    }
    if (write_aux && tid < MT)
        out[(size_t)NROWS * DDIM + 1 + row0 + tid] = (float)S->rmini[tid];

    #pragma unroll
    for (int off = 16; off >= 1; off >>= 1)
        lsq += __shfl_xor_sync(0xffffffffu, lsq, off);
    if ((tid & 31) == 0) S->sred[tid >> 5] = lsq;
    __syncthreads();
    if (tid == 0) {
        double s = 0.0;
        for (int i = 0; i < 8; i++) s += S->sred[i];
        atomicAdd(&g_msum, s);
    }
}

// ------------------- K2: filtered softmax entropy (warp/row, ~3 live entries/row)
// exp(l - M) == 0 / denormal (<6e-39) whenever d > dmin + 0.90; such terms change
// S, avg_probs, sample_entropy by < 1e-35 -- far below tolerance. M = (-dmin)/0.01
// equals max(l) exactly (division by positive constant is monotone).
__global__ __launch_bounds__(256)
void k2_soft() {
    int row  = (blockIdx.x * 256 + threadIdx.x) >> 5;
    int lane = threadIdx.x & 31;
    const float4* dr = (const float4*)(g_dist + (size_t)row * KCB);

    float dmin = g_rmin[row];
    float thr  = dmin + 0.90f;
    float M    = (-dmin) / 0.01f;

    float4 v[8];
    #pragma unroll
    for (int i = 0; i < 8; i++) v[i] = dr[i * 32 + lane];

    float S = 0.0f;
    #pragma unroll
    for (int i = 0; i < 8; i++) {
        if (v[i].x <= thr) S += expf((-v[i].x) / 0.01f - M);
        if (v[i].y <= thr) S += expf((-v[i].y) / 0.01f - M);
        if (v[i].z <= thr) S += expf((-v[i].z) / 0.01f - M);
        if (v[i].w <= thr) S += expf((-v[i].w) / 0.01f - M);
    }
    #pragma unroll
    for (int off = 16; off >= 1; off >>= 1)
        S += __shfl_xor_sync(0xffffffffu, S, off);

    float logS = logf(S);
    float accent = 0.0f;
    #pragma unroll
    for (int i = 0; i < 8; i++) {
        #pragma unroll
        for (int c = 0; c < 4; c++) {
            float d = (c == 0) ? v[i].x : (c == 1) ? v[i].y : (c == 2) ? v[i].z : v[i].w;
            if (d <= thr) {
                float sh = (-d) / 0.01f - M;
                float p  = expf(sh) / S;
                accent += p * (sh - logS);        // p * log_softmax (+1e-5 on logits is an fp32 no-op)
                atomicAdd(&g_avgp[i * 128 + lane * 4 + c], p);
            }
        }
    }
    #pragma unroll
    for (int off = 16; off >= 1; off >>= 1)
        accent += __shfl_xor_sync(0xffffffffu, accent, off);
    if (lane == 0) atomicAdd(&g_sample, (double)accent);
}

// ---------------------------------------------------------------- K3: final loss
__global__ void k3_final(float* out, int write_loss) {
    __shared__ float w[32];
    int t = threadIdx.x;   // 1024 threads
    float ap   = g_avgp[t] / 32768.0f;
    float term = ap * logf(ap + 1e-5f);
    #pragma unroll
    for (int off = 16; off >= 1; off >>= 1)
        term += __shfl_xor_sync(0xffffffffu, term, off);
    if ((t & 31) == 0) w[t >> 5] = term;
    __syncthreads();
    if (t == 0) {
        float tot = 0.0f;
        for (int i = 0; i < 32; i++) tot += w[i];
        float avg_ent = -tot;
        float samp    = -(float)(g_sample / 32768.0);
        float entropy = samp - avg_ent;
        float m       = (float)(g_msum / 8388608.0);
        float loss    = (m * 0.25f + m) + entropy * 0.1f;
        if (write_loss) out[(size_t)NROWS * DDIM] = loss;
    }
}

// ---------------------------------------------------------------- launch
extern "C" void kernel_launch(void* const* d_in, const int* in_sizes, int n_in,
                              void* d_out, int out_size) {
    const float* x  = (const float*)d_in[0];
    const float* cb = (const float*)d_in[1];
    if (n_in >= 2 && in_sizes[0] == KCB * DDIM && in_sizes[1] == NROWS * DDIM) {
        const float* tmp = x; x = cb; cb = tmp;   // defensive: (codebook, x) order
    }
    float* out = (float*)d_out;
    int aux = (out_size >= NROWS * DDIM + 1 + NROWS) ? 1 : 0;

    static int smem_set = 0;
    if (!smem_set) {
        cudaFuncSetAttribute(k1_main, cudaFuncAttributeMaxDynamicSharedMemorySize,
                             (int)sizeof(K1Smem));
        smem_set = 1;
    }

    k0_init<<<4, 256>>>(cb);
    k1_main<<<NROWS / MT, 256, sizeof(K1Smem)>>>(x, cb, out, aux);
    k2_soft<<<NROWS / 8, 256>>>();
    k3_final<<<1, 1024>>>(out, (out_size > NROWS * DDIM) ? 1 : 0);
}

// round 7
// speedup vs baseline: 1.7075x; 1.3856x over previous
#include <cuda_runtime.h>
#include <math.h>
#include <stdint.h>

#define NROWS 32768
#define DDIM  256
#define KCB   1024
#define MT    128

// scratch (static device arrays: allowed)
__device__ float  g_dist[(size_t)NROWS * KCB];   // 134 MB
__device__ float  g_rmin[NROWS];
__device__ float  g_b2[KCB];
__device__ float  g_avgp[KCB];
__device__ double g_sample;
__device__ double g_msum;

// ---------------------------------------------------------------- K0: init
__global__ void k0_init(const float* __restrict__ cb) {
    int t = blockIdx.x * blockDim.x + threadIdx.x;
    if (t < KCB) {
        const float4* r = (const float4*)(cb + (size_t)t * DDIM);
        double acc = 0.0;
        for (int i = 0; i < DDIM / 4; i++) {
            float4 v = r[i];
            acc += (double)v.x * v.x + (double)v.y * v.y
                 + (double)v.z * v.z + (double)v.w * v.w;
        }
        g_b2[t]   = (float)acc;
        g_avgp[t] = 0.0f;
    }
    if (t == 0) { g_sample = 0.0; g_msum = 0.0; }
}

// --------------- K1: fp32 SIMT GEMM, 8x8 thread tiles, fused argmin + gather
// 256 CTAs (MT=128 rows), 256 threads = 16x16 thread grid (tx: 16 cols of 8,
// ty: 16 rows of 8). Full A tile (128x256) staged in smem d-major; B chunks of
// 16 d x 128 cols double-buffered via registers. dist rounding = reference:
// fl(a2+b2) - fl(2*dot), dot accumulated d=0..255 in order.
#define ASTR 132
#define BSTR 132
#define BBUF (16 * BSTR)

__global__ __launch_bounds__(256, 1)
void k1_main(const float* __restrict__ x, const float* __restrict__ cb,
             float* __restrict__ out, int write_aux) {
    extern __shared__ float sm[];              // As[256][132] then Bs[2][16][132]
    __shared__ float  b2s[KCB];
    __shared__ float  a2s[MT];
    __shared__ float  rmind[MT];
    __shared__ int    rmini[MT];
    __shared__ double sred[8];

    float* As = sm;
    float* Bs = sm + 256 * ASTR;

    const int tid  = threadIdx.x;
    const int l    = tid & 31;
    const int tx   = tid & 15;
    const int ty   = tid >> 4;
    const int row0 = blockIdx.x * MT;

    for (int i = tid; i < KCB; i += 256) b2s[i] = g_b2[i];

    // per-row |x|^2 (double-acc; per-row constant error cancels in row argmin
    // and in shift-invariant softmax)
    if (tid < MT) {
        const float4* r = (const float4*)(x + (size_t)(row0 + tid) * DDIM);
        double acc = 0.0;
        #pragma unroll 4
        for (int i = 0; i < DDIM / 4; i++) {
            float4 v = r[i];
            acc += (double)v.x * v.x + (double)v.y * v.y
                 + (double)v.z * v.z + (double)v.w * v.w;
        }
        a2s[tid] = (float)acc;
    }

    // stage full A tile (transpose to d-major)
    {
        int arow = tid >> 1, db = (tid & 1) * 128;
        const float4* src = (const float4*)(x + (size_t)(row0 + arow) * DDIM + db);
        #pragma unroll
        for (int q = 0; q < 32; q++) {
            float4 v = src[q];
            int d = db + 4 * q;
            As[(d + 0) * ASTR + arow] = v.x;
            As[(d + 1) * ASTR + arow] = v.y;
            As[(d + 2) * ASTR + arow] = v.z;
            As[(d + 3) * ASTR + arow] = v.w;
        }
    }

    // B register prefetch helpers: thread covers (col = tid>>1, dhalf = (tid&1)*8)
    const int bcol = tid >> 1;
    const int bdh  = (tid & 1) * 8;
    float4 rb0, rb1;
    auto load_rb = [&](int p) {
        int nt = p >> 4, kc = p & 15;
        const float4* src = (const float4*)(cb + (size_t)(nt * 128 + bcol) * DDIM + kc * 16 + bdh);
        rb0 = src[0]; rb1 = src[1];
    };
    auto sts_rb = [&](int p) {
        float* dst = Bs + (p & 1) * BBUF + bdh * BSTR + bcol;
        dst[0 * BSTR] = rb0.x; dst[1 * BSTR] = rb0.y;
        dst[2 * BSTR] = rb0.z; dst[3 * BSTR] = rb0.w;
        dst[4 * BSTR] = rb1.x; dst[5 * BSTR] = rb1.y;
        dst[6 * BSTR] = rb1.z; dst[7 * BSTR] = rb1.w;
    };
    load_rb(0);
    sts_rb(0);

    // per-thread running argmin for its 8 rows
    float bd[8]; int bcidx[8];
    #pragma unroll
    for (int i = 0; i < 8; i++) { bd[i] = 3.402823466e38f; bcidx[i] = 0; }

    float a2r[8];   // filled after sync below

    float acc[8][8];

    for (int p = 0; p < 128; p++) {
        const int nt = p >> 4, kc = p & 15, buf = p & 1;
        if (p + 1 < 128) load_rb(p + 1);
        __syncthreads();                      // Bs[buf] stores + (p==0) staging visible
        if (p == 0) {
            #pragma unroll
            for (int i = 0; i < 8; i++) a2r[i] = a2s[ty * 8 + i];
        }
        if (kc == 0) {
            #pragma unroll
            for (int i = 0; i < 8; i++)
                #pragma unroll
                for (int j = 0; j < 8; j++) acc[i][j] = 0.0f;
        }

        const float* bbase = Bs + buf * BBUF;
        #pragma unroll
        for (int dd = 0; dd < 16; dd++) {
            const float* arow = As + (kc * 16 + dd) * ASTR + ty * 8;
            const float* brow = bbase + dd * BSTR + tx * 8;
            float4 av0 = *(const float4*)(arow);
            float4 av1 = *(const float4*)(arow + 4);
            float4 bv0 = *(const float4*)(brow);
            float4 bv1 = *(const float4*)(brow + 4);
            float a[8] = {av0.x, av0.y, av0.z, av0.w, av1.x, av1.y, av1.z, av1.w};
            float b[8] = {bv0.x, bv0.y, bv0.z, bv0.w, bv1.x, bv1.y, bv1.z, bv1.w};
            #pragma unroll
            for (int i = 0; i < 8; i++)
                #pragma unroll
                for (int j = 0; j < 8; j++)
                    acc[i][j] = fmaf(a[i], b[j], acc[i][j]);
        }

        if (kc == 15) {
            // epilogue for N-tile nt: dist (reference rounding), scratch store,
            // per-thread argmin (cols ascending -> first-index ties via strict <)
            const int c0 = nt * 128 + tx * 8;
            #pragma unroll
            for (int i = 0; i < 8; i++) {
                int R = ty * 8 + i;
                float a2 = a2r[i];
                float dv[8];
                #pragma unroll
                for (int j = 0; j < 8; j++) {
                    float t = a2 + b2s[c0 + j];          // fl(a2 + b2)
                    float d = t - 2.0f * acc[i][j];      // fl(t - 2ab)
                    dv[j] = d;
                    if (d < bd[i]) { bd[i] = d; bcidx[i] = c0 + j; }
                }
                float4* dst = (float4*)(g_dist + (size_t)(row0 + R) * KCB + c0);
                dst[0] = make_float4(dv[0], dv[1], dv[2], dv[3]);
                dst[1] = make_float4(dv[4], dv[5], dv[6], dv[7]);
            }
        }

        if (p + 1 < 128) sts_rb(p + 1);       // writes other buffer: no race
    }

    // lex (d, col) reduce across the 16 tx lanes sharing each row (same warp half)
    #pragma unroll
    for (int i = 0; i < 8; i++) {
        float d = bd[i]; int c = bcidx[i];
        #pragma unroll
        for (int off = 8; off >= 1; off >>= 1) {
            float od = __shfl_xor_sync(0xffffffffu, d, off);
            int   oc = __shfl_xor_sync(0xffffffffu, c, off);
            if (od < d || (od == d && oc < c)) { d = od; c = oc; }
        }
        if ((l & 15) == 0) { rmind[ty * 8 + i] = d; rmini[ty * 8 + i] = c; }
    }
    __syncthreads();
    if (tid < MT) g_rmin[row0 + tid] = rmind[tid];

    // gather codebook[argmin], write quantized_st = fl(x + fl(q-x)), msum
    double lsq = 0.0;
    for (int it = 0; it < MT; it++) {
        int grow = row0 + it;
        int idx  = rmini[it];
        float xv   = x[(size_t)grow * DDIM + tid];
        float q    = cb[(size_t)idx * DDIM + tid];
        float diff = q - xv;
        out[(size_t)grow * DDIM + tid] = xv + diff;
        lsq += (double)diff * (double)diff;
    }
    if (write_aux && tid < MT)
        out[(size_t)NROWS * DDIM + 1 + row0 + tid] = (float)rmini[tid];

    #pragma unroll
    for (int off = 16; off >= 1; off >>= 1)
        lsq += __shfl_xor_sync(0xffffffffu, lsq, off);
    if ((tid & 31) == 0) sred[tid >> 5] = lsq;
    __syncthreads();
    if (tid == 0) {
        double s = 0.0;
        for (int i = 0; i < 8; i++) s += sred[i];
        atomicAdd(&g_msum, s);
    }
}

// ------------------- K2: filtered softmax entropy (warp/row, ~3 live entries/row)
// exp(l - M) == 0 / denormal (<6e-39) whenever d > dmin + 0.90; excluded terms
// perturb S / avg_probs / sample_entropy by < 1e-35. M = (-dmin)/0.01 = max(l)
// exactly (division by positive constant is monotone). Proven in round 2.
__global__ __launch_bounds__(256)
void k2_soft() {
    int row  = (blockIdx.x * 256 + threadIdx.x) >> 5;
    int lane = threadIdx.x & 31;
    const float4* dr = (const float4*)(g_dist + (size_t)row * KCB);

    float dmin = g_rmin[row];
    float thr  = dmin + 0.90f;
    float M    = (-dmin) / 0.01f;

    float4 v[8];
    #pragma unroll
    for (int i = 0; i < 8; i++) v[i] = dr[i * 32 + lane];

    float S = 0.0f;
    #pragma unroll
    for (int i = 0; i < 8; i++) {
        if (v[i].x <= thr) S += expf((-v[i].x) / 0.01f - M);
        if (v[i].y <= thr) S += expf((-v[i].y) / 0.01f - M);
        if (v[i].z <= thr) S += expf((-v[i].z) / 0.01f - M);
        if (v[i].w <= thr) S += expf((-v[i].w) / 0.01f - M);
    }
    #pragma unroll
    for (int off = 16; off >= 1; off >>= 1)
        S += __shfl_xor_sync(0xffffffffu, S, off);

    float logS = logf(S);
    float accent = 0.0f;
    #pragma unroll
    for (int i = 0; i < 8; i++) {
        #pragma unroll
        for (int c = 0; c < 4; c++) {
            float d = (c == 0) ? v[i].x : (c == 1) ? v[i].y : (c == 2) ? v[i].z : v[i].w;
            if (d <= thr) {
                float sh = (-d) / 0.01f - M;
                float p  = expf(sh) / S;
                accent += p * (sh - logS);   // p * log_softmax (+1e-5 is an fp32 no-op here)
                atomicAdd(&g_avgp[i * 128 + lane * 4 + c], p);
            }
        }
    }
    #pragma unroll
    for (int off = 16; off >= 1; off >>= 1)
        accent += __shfl_xor_sync(0xffffffffu, accent, off);
    if (lane == 0) atomicAdd(&g_sample, (double)accent);
}

// ---------------------------------------------------------------- K3: final loss
__global__ void k3_final(float* out, int write_loss) {
    __shared__ float w[32];
    int t = threadIdx.x;   // 1024 threads
    float ap   = g_avgp[t] / 32768.0f;
    float term = ap * logf(ap + 1e-5f);
    #pragma unroll
    for (int off = 16; off >= 1; off >>= 1)
        term += __shfl_xor_sync(0xffffffffu, term, off);
    if ((t & 31) == 0) w[t >> 5] = term;
    __syncthreads();
    if (t == 0) {
        float tot = 0.0f;
        for (int i = 0; i < 32; i++) tot += w[i];
        float avg_ent = -tot;
        float samp    = -(float)(g_sample / 32768.0);
        float entropy = samp - avg_ent;
        float m       = (float)(g_msum / 8388608.0);
        float loss    = (m * 0.25f + m) + entropy * 0.1f;
        if (write_loss) out[(size_t)NROWS * DDIM] = loss;
    }
}

// ---------------------------------------------------------------- launch
extern "C" void kernel_launch(void* const* d_in, const int* in_sizes, int n_in,
                              void* d_out, int out_size) {
    const float* x  = (const float*)d_in[0];
    const float* cb = (const float*)d_in[1];
    if (n_in >= 2 && in_sizes[0] == KCB * DDIM && in_sizes[1] == NROWS * DDIM) {
        const float* tmp = x; x = cb; cb = tmp;   // defensive: (codebook, x) order
    }
    float* out = (float*)d_out;
    int aux = (out_size >= NROWS * DDIM + 1 + NROWS) ? 1 : 0;

    static int init_done = 0;
    const int k1_smem = (256 * ASTR + 2 * 16 * BSTR) * 4;   // 152064 bytes
    if (!init_done) {
        cudaFuncSetAttribute(k1_main, cudaFuncAttributeMaxDynamicSharedMemorySize, k1_smem);
        init_done = 1;
    }

    k0_init<<<4, 256>>>(cb);
    k1_main<<<NROWS / MT, 256, k1_smem>>>(x, cb, out, aux);
    k2_soft<<<NROWS / 8, 256>>>();
    k3_final<<<1, 1024>>>(out, (out_size > NROWS * DDIM) ? 1 : 0);
}

// round 8
// speedup vs baseline: 1.8364x; 1.0755x over previous
#include <cuda_runtime.h>
#include <math.h>
#include <stdint.h>

#define NROWS 32768
#define DDIM  256
#define KCB   1024
#define MT    128
#define GRIDP 152          // persistent CTAs (GB300: 152 SMs)
#define NUNITS 2048        // 256 rowblocks x 8 colblocks (128x128xK units)

// scratch (static device arrays: allowed)
__device__ float              g_dist[(size_t)NROWS * KCB];   // 134 MB
__device__ unsigned long long g_key[NROWS];                  // (dist_bits<<32)|col
__device__ float              g_b2[KCB];
__device__ float              g_avgp[KCB];
__device__ double             g_sample;
__device__ double             g_msum;

// ---------------------------------------------------------------- K0: init
__global__ void k0_init(const float* __restrict__ cb) {
    int t = blockIdx.x * blockDim.x + threadIdx.x;   // grid covers 32768
    if (t < KCB) {
        const float4* r = (const float4*)(cb + (size_t)t * DDIM);
        double acc = 0.0;
        for (int i = 0; i < DDIM / 4; i++) {
            float4 v = r[i];
            acc += (double)v.x * v.x + (double)v.y * v.y
                 + (double)v.z * v.z + (double)v.w * v.w;
        }
        g_b2[t]   = (float)acc;
        g_avgp[t] = 0.0f;
    }
    if (t < NROWS) g_key[t] = 0xFFFFFFFFFFFFFFFFull;
    if (t == 0) { g_sample = 0.0; g_msum = 0.0; }
}

// --------------- K1: persistent fp32 SIMT GEMM, 8x8 thread tiles, unit queue
// 152 CTAs; unit = 128 rows x 128 cols x K=256. Contiguous static ranges so A
// restages only on rowblock change. dist rounding = reference:
// fl(a2+b2) - fl(2*dot), dot fmaf-chained d=0..255 in order (bit-same as R7).
#define ASTR 132
#define BSTR 132
#define BBUF (16 * BSTR)

__global__ __launch_bounds__(256, 1)
void k1_main(const float* __restrict__ x, const float* __restrict__ cb) {
    extern __shared__ float sm[];              // As[256][132] then Bs[2][16][132]
    __shared__ float a2s[MT];
    __shared__ float b2s[KCB];

    float* As = sm;
    float* Bs = sm + 256 * ASTR;

    const int tid = threadIdx.x;
    const int l   = tid & 31;
    const int tx  = tid & 15;
    const int ty  = tid >> 4;

    for (int i = tid; i < KCB; i += 256) b2s[i] = g_b2[i];

    const int u0 = (int)(((long long)blockIdx.x * NUNITS) / GRIDP);
    const int u1 = (int)(((long long)(blockIdx.x + 1) * NUNITS) / GRIDP);
    int cur_rb = -1;

    const int bcol = tid >> 1;                 // 0..127 (col within unit)
    const int bdh  = (tid & 1) * 8;            // d-half 0 / 8

    for (int u = u0; u < u1; u++) {
        const int rb   = u >> 3;
        const int cbk  = u & 7;
        const int row0 = rb * MT;
        const int c0   = cbk * 128;

        if (rb != cur_rb) {
            __syncthreads();                   // prior unit's As readers done
            int arow = tid >> 1, db = (tid & 1) * 128;
            const float4* src = (const float4*)(x + (size_t)(row0 + arow) * DDIM + db);
            #pragma unroll
            for (int q = 0; q < 32; q++) {
                float4 v = src[q];
                int d = db + 4 * q;
                As[(d + 0) * ASTR + arow] = v.x;
                As[(d + 1) * ASTR + arow] = v.y;
                As[(d + 2) * ASTR + arow] = v.z;
                As[(d + 3) * ASTR + arow] = v.w;
            }
            if (tid < MT) {
                const float4* r = (const float4*)(x + (size_t)(row0 + tid) * DDIM);
                double acc = 0.0;
                #pragma unroll 4
                for (int i = 0; i < DDIM / 4; i++) {
                    float4 v = r[i];
                    acc += (double)v.x * v.x + (double)v.y * v.y
                         + (double)v.z * v.z + (double)v.w * v.w;
                }
                a2s[tid] = (float)acc;         // visible after phase-0 sync
            }
            cur_rb = rb;
        }

        // B chunk prefetch (registers -> smem, double-buffered)
        float4 rbv0, rbv1;
        auto load_rb = [&](int kc) {
            const float4* src = (const float4*)(cb + (size_t)(c0 + bcol) * DDIM + kc * 16 + bdh);
            rbv0 = src[0]; rbv1 = src[1];
        };
        auto sts_rb = [&](int kc) {
            float* dst = Bs + (kc & 1) * BBUF + bdh * BSTR + bcol;
            dst[0 * BSTR] = rbv0.x; dst[1 * BSTR] = rbv0.y;
            dst[2 * BSTR] = rbv0.z; dst[3 * BSTR] = rbv0.w;
            dst[4 * BSTR] = rbv1.x; dst[5 * BSTR] = rbv1.y;
            dst[6 * BSTR] = rbv1.z; dst[7 * BSTR] = rbv1.w;
        };
        load_rb(0);
        sts_rb(0);                             // other buffer than prior unit's last: safe

        float a2r[8];
        float acc[8][8];
        #pragma unroll
        for (int i = 0; i < 8; i++)
            #pragma unroll
            for (int j = 0; j < 8; j++) acc[i][j] = 0.0f;

        for (int kc = 0; kc < 16; kc++) {
            if (kc + 1 < 16) load_rb(kc + 1);
            __syncthreads();
            if (kc == 0) {
                #pragma unroll
                for (int i = 0; i < 8; i++) a2r[i] = a2s[ty * 8 + i];
            }
            const float* bbase = Bs + (kc & 1) * BBUF;
            #pragma unroll
            for (int dd = 0; dd < 16; dd++) {
                const float* arow = As + (kc * 16 + dd) * ASTR + ty * 8;
                const float* brow = bbase + dd * BSTR + tx * 8;
                float4 av0 = *(const float4*)(arow);
                float4 av1 = *(const float4*)(arow + 4);
                float4 bv0 = *(const float4*)(brow);
                float4 bv1 = *(const float4*)(brow + 4);
                float a[8] = {av0.x, av0.y, av0.z, av0.w, av1.x, av1.y, av1.z, av1.w};
                float b[8] = {bv0.x, bv0.y, bv0.z, bv0.w, bv1.x, bv1.y, bv1.z, bv1.w};
                #pragma unroll
                for (int i = 0; i < 8; i++)
                    #pragma unroll
                    for (int j = 0; j < 8; j++)
                        acc[i][j] = fmaf(a[i], b[j], acc[i][j]);
            }
            if (kc + 1 < 16) sts_rb(kc + 1);   // writes other buffer: no race
        }

        // unit epilogue: dist (reference rounding), scratch store, lex argmin merge
        const int cc0 = c0 + tx * 8;
        #pragma unroll
        for (int i = 0; i < 8; i++) {
            int R = ty * 8 + i;
            float a2 = a2r[i];
            float bd = 3.402823466e38f; int bc = 0;
            float dv[8];
            #pragma unroll
            for (int j = 0; j < 8; j++) {
                float t = a2 + b2s[cc0 + j];     // fl(a2 + b2)
                float d = t - 2.0f * acc[i][j];  // fl(t - 2ab)
                dv[j] = d;
                if (d < bd) { bd = d; bc = cc0 + j; }   // cols ascend: first-index ties
            }
            float4* dst = (float4*)(g_dist + (size_t)(row0 + R) * KCB + cc0);
            dst[0] = make_float4(dv[0], dv[1], dv[2], dv[3]);
            dst[1] = make_float4(dv[4], dv[5], dv[6], dv[7]);
            #pragma unroll
            for (int off = 8; off >= 1; off >>= 1) {    // lex (d, col) over 16 tx lanes
                float od = __shfl_xor_sync(0xffffffffu, bd, off);
                int   oc = __shfl_xor_sync(0xffffffffu, bc, off);
                if (od < bd || (od == bd && oc < bc)) { bd = od; bc = oc; }
            }
            if ((l & 15) == 0) {
                unsigned long long key =
                    ((unsigned long long)__float_as_uint(bd) << 32) | (unsigned)bc;
                atomicMin(&g_key[row0 + R], key);       // dists > 0: bit-order = value-order
            }
        }
    }
}

// ------------------- K2: filtered softmax entropy (warp/row, ~3 live entries/row)
// exp(l - M) == 0 / denormal (<6e-39) whenever d > dmin + 0.90; excluded terms
// perturb S / avg_probs / sample_entropy by < 1e-35. M = (-dmin)/0.01 = max(l)
// exactly (division by positive constant is monotone). Proven rounds 2 & 7.
__global__ __launch_bounds__(256)
void k2_soft() {
    int row  = (blockIdx.x * 256 + threadIdx.x) >> 5;
    int lane = threadIdx.x & 31;
    const float4* dr = (const float4*)(g_dist + (size_t)row * KCB);

    float dmin = __uint_as_float((unsigned)(g_key[row] >> 32));
    float thr  = dmin + 0.90f;
    float M    = (-dmin) / 0.01f;

    float4 v[8];
    #pragma unroll
    for (int i = 0; i < 8; i++) v[i] = dr[i * 32 + lane];

    float S = 0.0f;
    #pragma unroll
    for (int i = 0; i < 8; i++) {
        if (v[i].x <= thr) S += expf((-v[i].x) / 0.01f - M);
        if (v[i].y <= thr) S += expf((-v[i].y) / 0.01f - M);
        if (v[i].z <= thr) S += expf((-v[i].z) / 0.01f - M);
        if (v[i].w <= thr) S += expf((-v[i].w) / 0.01f - M);
    }
    #pragma unroll
    for (int off = 16; off >= 1; off >>= 1)
        S += __shfl_xor_sync(0xffffffffu, S, off);

    float logS = logf(S);
    float accent = 0.0f;
    #pragma unroll
    for (int i = 0; i < 8; i++) {
        #pragma unroll
        for (int c = 0; c < 4; c++) {
            float d = (c == 0) ? v[i].x : (c == 1) ? v[i].y : (c == 2) ? v[i].z : v[i].w;
            if (d <= thr) {
                float sh = (-d) / 0.01f - M;
                float p  = expf(sh) / S;
                accent += p * (sh - logS);   // p * log_softmax (+1e-5 is an fp32 no-op here)
                atomicAdd(&g_avgp[i * 128 + lane * 4 + c], p);
            }
        }
    }
    #pragma unroll
    for (int off = 16; off >= 1; off >>= 1)
        accent += __shfl_xor_sync(0xffffffffu, accent, off);
    if (lane == 0) atomicAdd(&g_sample, (double)accent);
}

// ---------------- K2b: gather + quantized_st = fl(x + fl(q-x)) + indices + msum
__global__ __launch_bounds__(256)
void k2b_out(const float* __restrict__ x, const float* __restrict__ cb,
             float* __restrict__ out, int write_aux) {
    __shared__ int    idxs[MT];
    __shared__ double sred[8];
    const int tid  = threadIdx.x;
    const int row0 = blockIdx.x * MT;

    if (tid < MT) idxs[tid] = (int)(g_key[row0 + tid] & 0xFFFFFFFFull);
    __syncthreads();

    double lsq = 0.0;
    for (int it = 0; it < MT; it++) {
        int grow = row0 + it;
        int idx  = idxs[it];
        float xv   = x[(size_t)grow * DDIM + tid];
        float q    = cb[(size_t)idx * DDIM + tid];
        float diff = q - xv;
        out[(size_t)grow * DDIM + tid] = xv + diff;
        lsq += (double)diff * (double)diff;
    }
    if (write_aux && tid < MT)
        out[(size_t)NROWS * DDIM + 1 + row0 + tid] = (float)idxs[tid];

    #pragma unroll
    for (int off = 16; off >= 1; off >>= 1)
        lsq += __shfl_xor_sync(0xffffffffu, lsq, off);
    if ((tid & 31) == 0) sred[tid >> 5] = lsq;
    __syncthreads();
    if (tid == 0) {
        double s = 0.0;
        for (int i = 0; i < 8; i++) s += sred[i];
        atomicAdd(&g_msum, s);
    }
}

// ---------------------------------------------------------------- K3: final loss
__global__ void k3_final(float* out, int write_loss) {
    __shared__ float w[32];
    int t = threadIdx.x;   // 1024 threads
    float ap   = g_avgp[t] / 32768.0f;
    float term = ap * logf(ap + 1e-5f);
    #pragma unroll
    for (int off = 16; off >= 1; off >>= 1)
        term += __shfl_xor_sync(0xffffffffu, term, off);
    if ((t & 31) == 0) w[t >> 5] = term;
    __syncthreads();
    if (t == 0) {
        float tot = 0.0f;
        for (int i = 0; i < 32; i++) tot += w[i];
        float avg_ent = -tot;
        float samp    = -(float)(g_sample / 32768.0);
        float entropy = samp - avg_ent;
        float m       = (float)(g_msum / 8388608.0);
        float loss    = (m * 0.25f + m) + entropy * 0.1f;
        if (write_loss) out[(size_t)NROWS * DDIM] = loss;
    }
}

// ---------------------------------------------------------------- launch
extern "C" void kernel_launch(void* const* d_in, const int* in_sizes, int n_in,
                              void* d_out, int out_size) {
    const float* x  = (const float*)d_in[0];
    const float* cb = (const float*)d_in[1];
    if (n_in >= 2 && in_sizes[0] == KCB * DDIM && in_sizes[1] == NROWS * DDIM) {
        const float* tmp = x; x = cb; cb = tmp;   // defensive: (codebook, x) order
    }
    float* out = (float*)d_out;
    int aux = (out_size >= NROWS * DDIM + 1 + NROWS) ? 1 : 0;

    static int init_done = 0;
    const int k1_smem = (256 * ASTR + 2 * 16 * BSTR) * 4;   // 152064 bytes
    if (!init_done) {
        cudaFuncSetAttribute(k1_main, cudaFuncAttributeMaxDynamicSharedMemorySize, k1_smem);
        init_done = 1;
    }

    k0_init<<<NROWS / 256, 256>>>(cb);
    k1_main<<<GRIDP, 256, k1_smem>>>(x, cb);
    k2_soft<<<NROWS / 8, 256>>>();
    k2b_out<<<NROWS / MT, 256>>>(x, cb, out, aux);
    k3_final<<<1, 1024>>>(out, (out_size > NROWS * DDIM) ? 1 : 0);
}